// round 15
// baseline (speedup 1.0000x reference)
#include <cuda_runtime.h>
#include <cuda_bf16.h>
#include <cuda_fp16.h>
#include <cstdint>

#define NN 50000
#define NE 1600000
#define IN_F 256
#define OUT_C 128   // H*F
#define NH 4
#define NEG 0.2f

typedef unsigned long long u64;

// scratch (allocation-free rule: __device__ globals)
__device__ __align__(16) float  g_h[NN * OUT_C];     // projected features fp32 [N,128]
__device__ __align__(16) __half g_hh[NN * OUT_C];    // fp16 copy for gather   [N,128]
__device__ __align__(16) float  g_el[NN * NH];       // left logits  [N,4]
__device__ __align__(16) float  g_er[NN * NH];       // right logits [N,4]
__device__ int g_cnt[NN];                            // in-degree histogram
__device__ int g_off[NN + 1];                        // CSR offsets (by dst)
__device__ int g_bsum[64];                           // per-block scan sums
__device__ __align__(16) int g_rank[NE];             // edge rank within its dst
__device__ int g_csr_src[NE];                        // src node per CSR slot

// packed fp32x2 FMA (sm_103a FFMA2; only reachable via PTX)
#define FMA2(d, a, b, c) \
    asm("fma.rn.f32x2 %0, %1, %2, %3;" : "=l"(d) : "l"(a), "l"(b), "l"(c))
#define PACKF2(d, lo, hi) \
    asm("mov.b64 %0, {%1, %2};" : "=l"(d) : "f"(lo), "f"(hi))
#define UNPACKF2(lo, hi, s) \
    asm("mov.b64 {%0, %1}, %2;" : "=f"(lo), "=f"(hi) : "l"(s))

// ---------------------------------------------------------------------------
// CSR build: zero -> hist(+rank) -> scan1 -> scan3(w/ inline block-sum) -> scatter
// ---------------------------------------------------------------------------
__global__ void zero_cnt_kernel() {
    int i = blockIdx.x * blockDim.x + threadIdx.x;
    if (i < NN) g_cnt[i] = 0;
}

__global__ void hist_kernel(const int* __restrict__ dst) {
    int base = (blockIdx.x * blockDim.x + threadIdx.x) * 8;
    if (base >= NE) return;
    int4 d0 = *(const int4*)(dst + base);
    int4 d1 = *(const int4*)(dst + base + 4);
    int d[8] = {d0.x, d0.y, d0.z, d0.w, d1.x, d1.y, d1.z, d1.w};
    int r[8];
#pragma unroll
    for (int j = 0; j < 8; j++) r[j] = atomicAdd(&g_cnt[d[j]], 1);
    *(int4*)(g_rank + base)     = make_int4(r[0], r[1], r[2], r[3]);
    *(int4*)(g_rank + base + 4) = make_int4(r[4], r[5], r[6], r[7]);
}

// phase 1: per-block exclusive scan of 1024 counts + block totals (49 blocks)
__global__ __launch_bounds__(1024) void scan1_kernel() {
    __shared__ int ssum[1024];
    int b = blockIdx.x, t = threadIdx.x;
    int i = b * 1024 + t;
    int c = (i < NN) ? g_cnt[i] : 0;
    ssum[t] = c;
    __syncthreads();
    for (int off = 1; off < 1024; off <<= 1) {
        int v = (t >= off) ? ssum[t - off] : 0;
        __syncthreads();
        ssum[t] += v;
        __syncthreads();
    }
    if (i <= NN) g_off[i] = ssum[t] - c;   // block-local exclusive prefix
    if (t == 1023) g_bsum[b] = ssum[1023];
}

// phase 2 (merged): each block computes sum of g_bsum[0..b-1] inline, adds it.
__global__ __launch_bounds__(1024) void scan3_kernel() {
    __shared__ int s[64];
    int b = blockIdx.x, t = threadIdx.x;
    if (t < 64) s[t] = (t < b) ? g_bsum[t] : 0;   // b <= 48 < 64
    __syncthreads();
#pragma unroll
    for (int off = 32; off >= 1; off >>= 1) {
        if (t < off) s[t] += s[t + off];
        __syncthreads();
    }
    int add = s[0];
    int i = b * 1024 + t;
    if (i <= NN) g_off[i] += add;
}

__global__ void scatter_kernel(const int* __restrict__ src, const int* __restrict__ dst) {
    int base = (blockIdx.x * blockDim.x + threadIdx.x) * 8;
    if (base >= NE) return;
    int4 d0 = *(const int4*)(dst + base);
    int4 d1 = *(const int4*)(dst + base + 4);
    int4 s0 = *(const int4*)(src + base);
    int4 s1 = *(const int4*)(src + base + 4);
    int4 r0 = *(const int4*)(g_rank + base);
    int4 r1 = *(const int4*)(g_rank + base + 4);
    int d[8] = {d0.x, d0.y, d0.z, d0.w, d1.x, d1.y, d1.z, d1.w};
    int s[8] = {s0.x, s0.y, s0.z, s0.w, s1.x, s1.y, s1.z, s1.w};
    int r[8] = {r0.x, r0.y, r0.z, r0.w, r1.x, r1.y, r1.z, r1.w};
    int o[8];
#pragma unroll
    for (int j = 0; j < 8; j++) o[j] = g_off[d[j]];
#pragma unroll
    for (int j = 0; j < 8; j++) g_csr_src[o[j] + r[j]] = s[j];
}

// ---------------------------------------------------------------------------
// Projection: h = feat @ W^T via bf16-split tensor-core GEMM.
// ---------------------------------------------------------------------------
#define SPIT 40

__device__ __forceinline__ void bsplit(float x, __nv_bfloat16& hi, __nv_bfloat16& lo) {
    hi = __float2bfloat16_rn(x);
    lo = __float2bfloat16_rn(x - __bfloat162float(hi));
}

__device__ __forceinline__ void ldm_x4(unsigned* r, const __nv_bfloat16* p) {
    unsigned a = (unsigned)__cvta_generic_to_shared(p);
    asm volatile("ldmatrix.sync.aligned.m8n8.x4.shared.b16 {%0,%1,%2,%3}, [%4];"
                 : "=r"(r[0]), "=r"(r[1]), "=r"(r[2]), "=r"(r[3]) : "r"(a));
}

__device__ __forceinline__ void mma16816(float* c, const unsigned* a,
                                         unsigned b0, unsigned b1) {
    asm volatile("mma.sync.aligned.m16n8k16.row.col.f32.bf16.bf16.f32 "
                 "{%0,%1,%2,%3},{%4,%5,%6,%7},{%8,%9},{%0,%1,%2,%3};"
                 : "+f"(c[0]), "+f"(c[1]), "+f"(c[2]), "+f"(c[3])
                 : "r"(a[0]), "r"(a[1]), "r"(a[2]), "r"(a[3]), "r"(b0), "r"(b1));
}

__global__ __launch_bounds__(256) void proj_mma_kernel(
    const float* __restrict__ feat, const float* __restrict__ W)
{
    __shared__ __nv_bfloat16 sAhi[128][SPIT];
    __shared__ __nv_bfloat16 sAlo[128][SPIT];
    __shared__ __nv_bfloat16 sBhi[128][SPIT];
    __shared__ __nv_bfloat16 sBlo[128][SPIT];

    int t = threadIdx.x;
    int lane = t & 31;
    int wid = t >> 5;
    int wm = wid & 3;
    int wn = wid >> 2;
    int node0 = blockIdx.x * 128;

    float acc[2][8][4];
#pragma unroll
    for (int i = 0; i < 2; i++)
#pragma unroll
        for (int j = 0; j < 8; j++)
#pragma unroll
            for (int q = 0; q < 4; q++) acc[i][j][q] = 0.0f;

    for (int k0 = 0; k0 < IN_F; k0 += 32) {
#pragma unroll
        for (int j = 0; j < 4; j++) {
            int id = t + j * 256;            // 0..1023
            int row = id >> 3;
            int c4 = (id & 7) * 4;
            int node = node0 + row;
            if (node >= NN) node = NN - 1;
            float4 v = *(const float4*)(feat + (long)node * IN_F + k0 + c4);
            bsplit(v.x, sAhi[row][c4 + 0], sAlo[row][c4 + 0]);
            bsplit(v.y, sAhi[row][c4 + 1], sAlo[row][c4 + 1]);
            bsplit(v.z, sAhi[row][c4 + 2], sAlo[row][c4 + 2]);
            bsplit(v.w, sAhi[row][c4 + 3], sAlo[row][c4 + 3]);
        }
#pragma unroll
        for (int j = 0; j < 4; j++) {
            int id = t + j * 256;
            int row = id >> 3;
            int c4 = (id & 7) * 4;
            float4 v = *(const float4*)(W + (long)row * IN_F + k0 + c4);
            bsplit(v.x, sBhi[row][c4 + 0], sBlo[row][c4 + 0]);
            bsplit(v.y, sBhi[row][c4 + 1], sBlo[row][c4 + 1]);
            bsplit(v.z, sBhi[row][c4 + 2], sBlo[row][c4 + 2]);
            bsplit(v.w, sBhi[row][c4 + 3], sBlo[row][c4 + 3]);
        }
        __syncthreads();

#pragma unroll
        for (int ks = 0; ks < 2; ks++) {
            int koff = ks * 16;
            unsigned ahi[2][4], alo[2][4];
#pragma unroll
            for (int mt = 0; mt < 2; mt++) {
                int row = wm * 32 + mt * 16 + (lane & 15);
                int col = koff + (lane >> 4) * 8;
                ldm_x4(ahi[mt], &sAhi[row][col]);
                ldm_x4(alo[mt], &sAlo[row][col]);
            }
            unsigned bhi[4][4], blo[4][4];
#pragma unroll
            for (int ng = 0; ng < 4; ng++) {
                int row = wn * 64 + ng * 16 + (lane & 7) + ((lane >> 4) << 3);
                int col = koff + ((lane >> 3) & 1) * 8;
                ldm_x4(bhi[ng], &sBhi[row][col]);
                ldm_x4(blo[ng], &sBlo[row][col]);
            }
#pragma unroll
            for (int mt = 0; mt < 2; mt++)
#pragma unroll
                for (int ng = 0; ng < 4; ng++)
#pragma unroll
                    for (int hf = 0; hf < 2; hf++) {
                        float* c = acc[mt][ng * 2 + hf];
                        mma16816(c, ahi[mt], bhi[ng][hf * 2], bhi[ng][hf * 2 + 1]);
                        mma16816(c, ahi[mt], blo[ng][hf * 2], blo[ng][hf * 2 + 1]);
                        mma16816(c, alo[mt], bhi[ng][hf * 2], bhi[ng][hf * 2 + 1]);
                    }
        }
        __syncthreads();
    }

    // epilogue: C fragment -> g_h (fp32) + g_hh (fp16)
    int grp = lane >> 2;
    int tg = lane & 3;
#pragma unroll
    for (int mt = 0; mt < 2; mt++) {
#pragma unroll
        for (int nt = 0; nt < 8; nt++) {
            int row = node0 + wm * 32 + mt * 16 + grp;
            int col = wn * 64 + nt * 8 + tg * 2;
            float* c = acc[mt][nt];
            if (row < NN) {
                *(float2*)(g_h + (long)row * OUT_C + col) = make_float2(c[0], c[1]);
                *(__half2*)(g_hh + (long)row * OUT_C + col) = __floats2half2_rn(c[0], c[1]);
            }
            if (row + 8 < NN) {
                *(float2*)(g_h + (long)(row + 8) * OUT_C + col) = make_float2(c[2], c[3]);
                *(__half2*)(g_hh + (long)(row + 8) * OUT_C + col) = __floats2half2_rn(c[2], c[3]);
            }
        }
    }
}

// ---------------------------------------------------------------------------
// el/er: per (node, head) dot of h row-chunk with attn vectors (L2-resident)
// ---------------------------------------------------------------------------
__global__ void elr_kernel(const float* __restrict__ al, const float* __restrict__ ar) {
    int i = blockIdx.x * blockDim.x + threadIdx.x;   // node*NH + head
    if (i >= NN * NH) return;
    int node = i >> 2;
    int head = i & 3;
    const float* hp = g_h + (long)node * OUT_C + head * 32;
    float sl = 0.f, sr = 0.f;
#pragma unroll
    for (int j = 0; j < 8; j++) {
        float4 v = *(const float4*)(hp + j * 4);
        float4 a = *(const float4*)(al + head * 32 + j * 4);
        float4 b = *(const float4*)(ar + head * 32 + j * 4);
        sl += v.x * a.x + v.y * a.y + v.z * a.z + v.w * a.w;
        sr += v.x * b.x + v.y * b.y + v.z * b.z + v.w * b.w;
    }
    g_el[i] = sl;
    g_er[i] = sr;
}

// ---------------------------------------------------------------------------
// Fused softmax + aggregation: single-phase, half-warp per edge (R11 layout),
// accumulators as packed f32x2 -> FFMA2 halves FMA issue count. Arithmetic is
// bitwise identical to scalar FFMA (fma.rn.f32x2 = 2 IEEE FMAs).
// ---------------------------------------------------------------------------
__global__ __launch_bounds__(256) void agg_kernel(const float* __restrict__ bias,
                                                  float* __restrict__ out)
{
    int wib  = threadIdx.x >> 5;
    int lane = threadIdx.x & 31;
    int node = blockIdx.x * 8 + wib;
    if (node >= NN) return;

    int beg = g_off[node];
    int end = g_off[node + 1];

    int half = lane >> 4;      // which edge of the pair
    int hl   = lane & 15;      // lane within half-warp
    int hd2  = hl >> 2;        // head for my column range

    const float erv = g_er[node * NH + hd2];

    float dsum = 0.f;
    u64 acc2[4];
#pragma unroll
    for (int k = 0; k < 4; k++) acc2[k] = 0ull;   // packed (0.f, 0.f)

    const long colo = (long)hl * 8;   // fp16 column offset for this lane

    int e0 = beg;
    // main loop: 4 edges per warp iteration (2 per half-warp)
    for (; e0 + 3 < end; e0 += 4) {
        int eA = e0 + half * 2;
        int sA = g_csr_src[eA];
        int sB = g_csr_src[eA + 1];
        float lA = g_el[sA * NH + hd2];
        float lB = g_el[sB * NH + hd2];
        uint4 hA = *(const uint4*)((const char*)g_hh + ((long)sA * OUT_C + colo) * 2);
        uint4 hB = *(const uint4*)((const char*)g_hh + ((long)sB * OUT_C + colo) * 2);

        float xA = lA + erv; xA = xA >= 0.f ? xA : NEG * xA;
        float xB = lB + erv; xB = xB >= 0.f ? xB : NEG * xB;
        float aA = __expf(xA);
        float aB = __expf(xB);
        dsum += aA + aB;

        u64 aA2, aB2;
        PACKF2(aA2, aA, aA);
        PACKF2(aB2, aB, aB);

        float2 f; u64 p;
        f = __half22float2(*(const __half2*)&hA.x); PACKF2(p, f.x, f.y); FMA2(acc2[0], p, aA2, acc2[0]);
        f = __half22float2(*(const __half2*)&hA.y); PACKF2(p, f.x, f.y); FMA2(acc2[1], p, aA2, acc2[1]);
        f = __half22float2(*(const __half2*)&hA.z); PACKF2(p, f.x, f.y); FMA2(acc2[2], p, aA2, acc2[2]);
        f = __half22float2(*(const __half2*)&hA.w); PACKF2(p, f.x, f.y); FMA2(acc2[3], p, aA2, acc2[3]);
        f = __half22float2(*(const __half2*)&hB.x); PACKF2(p, f.x, f.y); FMA2(acc2[0], p, aB2, acc2[0]);
        f = __half22float2(*(const __half2*)&hB.y); PACKF2(p, f.x, f.y); FMA2(acc2[1], p, aB2, acc2[1]);
        f = __half22float2(*(const __half2*)&hB.z); PACKF2(p, f.x, f.y); FMA2(acc2[2], p, aB2, acc2[2]);
        f = __half22float2(*(const __half2*)&hB.w); PACKF2(p, f.x, f.y); FMA2(acc2[3], p, aB2, acc2[3]);
    }
    // tail: up to 3 edges, parity-split across halves
    for (; e0 < end; e0 += 2) {
        int e = e0 + half;
        if (e < end) {
            int s = g_csr_src[e];
            float l = g_el[s * NH + hd2];
            uint4 hv = *(const uint4*)((const char*)g_hh + ((long)s * OUT_C + colo) * 2);
            float x = l + erv; x = x >= 0.f ? x : NEG * x;
            float a = __expf(x);
            dsum += a;
            u64 a2;
            PACKF2(a2, a, a);
            float2 f; u64 p;
            f = __half22float2(*(const __half2*)&hv.x); PACKF2(p, f.x, f.y); FMA2(acc2[0], p, a2, acc2[0]);
            f = __half22float2(*(const __half2*)&hv.y); PACKF2(p, f.x, f.y); FMA2(acc2[1], p, a2, acc2[1]);
            f = __half22float2(*(const __half2*)&hv.z); PACKF2(p, f.x, f.y); FMA2(acc2[2], p, a2, acc2[2]);
            f = __half22float2(*(const __half2*)&hv.w); PACKF2(p, f.x, f.y); FMA2(acc2[3], p, a2, acc2[3]);
        }
    }

    // unpack accumulators
    float acc8[8];
#pragma unroll
    for (int k = 0; k < 4; k++) {
        UNPACKF2(acc8[k * 2], acc8[k * 2 + 1], acc2[k]);
    }

    // merge the two half-warp partial sums (same columns at lane ^ 16)
#pragma unroll
    for (int k = 0; k < 8; k++)
        acc8[k] += __shfl_xor_sync(0xffffffffu, acc8[k], 16);

    // reduce denominator over the 8-lane same-head orbit (4x replication)
    dsum += __shfl_xor_sync(0xffffffffu, dsum, 16);
    dsum += __shfl_xor_sync(0xffffffffu, dsum, 1);
    dsum += __shfl_xor_sync(0xffffffffu, dsum, 2);
    float dn = dsum * 0.25f;
    float rdn = (dn > 0.f) ? (1.0f / dn) : 1.0f;

    if (half == 0) {
        float4 b0 = *(const float4*)(bias + hl * 8);
        float4 b1 = *(const float4*)(bias + hl * 8 + 4);
        float4 o0, o1;
        o0.x = acc8[0] * rdn + b0.x; o0.y = acc8[1] * rdn + b0.y;
        o0.z = acc8[2] * rdn + b0.z; o0.w = acc8[3] * rdn + b0.w;
        o1.x = acc8[4] * rdn + b1.x; o1.y = acc8[5] * rdn + b1.y;
        o1.z = acc8[6] * rdn + b1.z; o1.w = acc8[7] * rdn + b1.w;
        *(float4*)(out + (long)node * OUT_C + hl * 8)     = o0;
        *(float4*)(out + (long)node * OUT_C + hl * 8 + 4) = o1;
    }
}

// ---------------------------------------------------------------------------
// Launch: fork-join so the CSR build (stream s2) overlaps the projection GEMM.
// ---------------------------------------------------------------------------
extern "C" void kernel_launch(void* const* d_in, const int* in_sizes, int n_in,
                              void* d_out, int out_size) {
    const float* feat = (const float*)d_in[0];
    const float* W    = (const float*)d_in[1];
    const float* al   = (const float*)d_in[2];
    const float* ar   = (const float*)d_in[3];
    const float* bias = (const float*)d_in[4];
    const int*   src  = (const int*)d_in[5];
    const int*   dst  = (const int*)d_in[6];
    float* out = (float*)d_out;

    static cudaStream_t s2 = nullptr;
    static cudaEvent_t ev_fork = nullptr, ev_join = nullptr;
    if (s2 == nullptr) {
        cudaStreamCreateWithFlags(&s2, cudaStreamNonBlocking);
        cudaEventCreateWithFlags(&ev_fork, cudaEventDisableTiming);
        cudaEventCreateWithFlags(&ev_join, cudaEventDisableTiming);
    }

    // fork: s2 joins the capture via the event dependency
    cudaEventRecord(ev_fork, 0);
    cudaStreamWaitEvent(s2, ev_fork, 0);

    // branch A (s2): CSR build
    zero_cnt_kernel<<<(NN + 255) / 256, 256, 0, s2>>>();
    hist_kernel<<<(NE / 8 + 255) / 256, 256, 0, s2>>>(dst);
    scan1_kernel<<<49, 1024, 0, s2>>>();
    scan3_kernel<<<49, 1024, 0, s2>>>();
    scatter_kernel<<<(NE / 8 + 255) / 256, 256, 0, s2>>>(src, dst);

    // branch B (main stream): projection + logits
    proj_mma_kernel<<<(NN + 127) / 128, 256>>>(feat, W);
    elr_kernel<<<(NN * NH + 255) / 256, 256>>>(al, ar);

    // join
    cudaEventRecord(ev_join, s2);
    cudaStreamWaitEvent(0, ev_join, 0);

    agg_kernel<<<(NN + 7) / 8, 256>>>(bias, out);
}

// round 16
// speedup vs baseline: 1.1268x; 1.1268x over previous
#include <cuda_runtime.h>
#include <cuda_bf16.h>
#include <cuda_fp16.h>
#include <cstdint>

#define NN 50000
#define NE 1600000
#define IN_F 256
#define OUT_C 128   // H*F
#define NH 4
#define NEG 0.2f

typedef unsigned long long u64;

// scratch (allocation-free rule: __device__ globals)
__device__ __align__(16) __half g_hh[NN * OUT_C];    // projected features fp16 [N,128]
__device__ __align__(16) float  g_el[NN * NH];       // left logits  [N,4]
__device__ __align__(16) float  g_er[NN * NH];       // right logits [N,4]
__device__ int g_cnt[NN];                            // in-degree histogram (zero-init; re-zeroed by scan1)
__device__ int g_off[NN + 1];                        // CSR offsets (by dst)
__device__ int g_bsum[64];                           // per-block scan sums
__device__ __align__(16) int g_rank[NE];             // edge rank within its dst
__device__ int g_csr_src[NE];                        // src node per CSR slot

// packed fp32x2 FMA (sm_103a FFMA2; only reachable via PTX)
#define FMA2(d, a, b, c) \
    asm("fma.rn.f32x2 %0, %1, %2, %3;" : "=l"(d) : "l"(a), "l"(b), "l"(c))
#define PACKF2(d, lo, hi) \
    asm("mov.b64 %0, {%1, %2};" : "=l"(d) : "f"(lo), "f"(hi))
#define UNPACKF2(lo, hi, s) \
    asm("mov.b64 {%0, %1}, %2;" : "=f"(lo), "=f"(hi) : "l"(s))

// ---------------------------------------------------------------------------
// CSR build: hist(+rank) -> scan1(re-zeroes cnt) -> scan3 -> scatter
// ---------------------------------------------------------------------------
__global__ void hist_kernel(const int* __restrict__ dst) {
    int base = (blockIdx.x * blockDim.x + threadIdx.x) * 8;
    if (base >= NE) return;
    int4 d0 = *(const int4*)(dst + base);
    int4 d1 = *(const int4*)(dst + base + 4);
    int d[8] = {d0.x, d0.y, d0.z, d0.w, d1.x, d1.y, d1.z, d1.w};
    int r[8];
#pragma unroll
    for (int j = 0; j < 8; j++) r[j] = atomicAdd(&g_cnt[d[j]], 1);
    *(int4*)(g_rank + base)     = make_int4(r[0], r[1], r[2], r[3]);
    *(int4*)(g_rank + base + 4) = make_int4(r[4], r[5], r[6], r[7]);
}

// phase 1: per-block exclusive scan of 1024 counts + block totals (49 blocks).
// Also re-zeroes g_cnt (nothing reads it afterwards) so the next replay's
// hist starts from zeros without a dedicated zero kernel.
__global__ __launch_bounds__(1024) void scan1_kernel() {
    __shared__ int ssum[1024];
    int b = blockIdx.x, t = threadIdx.x;
    int i = b * 1024 + t;
    int c = 0;
    if (i < NN) {
        c = g_cnt[i];
        g_cnt[i] = 0;
    }
    ssum[t] = c;
    __syncthreads();
    for (int off = 1; off < 1024; off <<= 1) {
        int v = (t >= off) ? ssum[t - off] : 0;
        __syncthreads();
        ssum[t] += v;
        __syncthreads();
    }
    if (i <= NN) g_off[i] = ssum[t] - c;   // block-local exclusive prefix
    if (t == 1023) g_bsum[b] = ssum[1023];
}

// phase 2 (merged): each block computes sum of g_bsum[0..b-1] inline, adds it.
__global__ __launch_bounds__(1024) void scan3_kernel() {
    __shared__ int s[64];
    int b = blockIdx.x, t = threadIdx.x;
    if (t < 64) s[t] = (t < b) ? g_bsum[t] : 0;   // b <= 48 < 64
    __syncthreads();
#pragma unroll
    for (int off = 32; off >= 1; off >>= 1) {
        if (t < off) s[t] += s[t + off];
        __syncthreads();
    }
    int add = s[0];
    int i = b * 1024 + t;
    if (i <= NN) g_off[i] += add;
}

__global__ void scatter_kernel(const int* __restrict__ src, const int* __restrict__ dst) {
    int base = (blockIdx.x * blockDim.x + threadIdx.x) * 8;
    if (base >= NE) return;
    int4 d0 = *(const int4*)(dst + base);
    int4 d1 = *(const int4*)(dst + base + 4);
    int4 s0 = *(const int4*)(src + base);
    int4 s1 = *(const int4*)(src + base + 4);
    int4 r0 = *(const int4*)(g_rank + base);
    int4 r1 = *(const int4*)(g_rank + base + 4);
    int d[8] = {d0.x, d0.y, d0.z, d0.w, d1.x, d1.y, d1.z, d1.w};
    int s[8] = {s0.x, s0.y, s0.z, s0.w, s1.x, s1.y, s1.z, s1.w};
    int r[8] = {r0.x, r0.y, r0.z, r0.w, r1.x, r1.y, r1.z, r1.w};
    int o[8];
#pragma unroll
    for (int j = 0; j < 8; j++) o[j] = g_off[d[j]];
#pragma unroll
    for (int j = 0; j < 8; j++) g_csr_src[o[j] + r[j]] = s[j];
}

// ---------------------------------------------------------------------------
// Projection: h = feat @ W^T via bf16-split tensor-core GEMM.
// Epilogue fuses el/er: each (node, head) dot is wholly within one warp
// (head h cols 32h..32h+31 are inside warp wn=h/2's 64-col tile), reduced
// over the 4-lane tg group via shfl. fp32 h is never materialized.
// ---------------------------------------------------------------------------
#define SPIT 40

__device__ __forceinline__ void bsplit(float x, __nv_bfloat16& hi, __nv_bfloat16& lo) {
    hi = __float2bfloat16_rn(x);
    lo = __float2bfloat16_rn(x - __bfloat162float(hi));
}

__device__ __forceinline__ void ldm_x4(unsigned* r, const __nv_bfloat16* p) {
    unsigned a = (unsigned)__cvta_generic_to_shared(p);
    asm volatile("ldmatrix.sync.aligned.m8n8.x4.shared.b16 {%0,%1,%2,%3}, [%4];"
                 : "=r"(r[0]), "=r"(r[1]), "=r"(r[2]), "=r"(r[3]) : "r"(a));
}

__device__ __forceinline__ void mma16816(float* c, const unsigned* a,
                                         unsigned b0, unsigned b1) {
    asm volatile("mma.sync.aligned.m16n8k16.row.col.f32.bf16.bf16.f32 "
                 "{%0,%1,%2,%3},{%4,%5,%6,%7},{%8,%9},{%0,%1,%2,%3};"
                 : "+f"(c[0]), "+f"(c[1]), "+f"(c[2]), "+f"(c[3])
                 : "r"(a[0]), "r"(a[1]), "r"(a[2]), "r"(a[3]), "r"(b0), "r"(b1));
}

__global__ __launch_bounds__(256) void proj_mma_kernel(
    const float* __restrict__ feat, const float* __restrict__ W,
    const float* __restrict__ al, const float* __restrict__ ar)
{
    __shared__ __nv_bfloat16 sAhi[128][SPIT];
    __shared__ __nv_bfloat16 sAlo[128][SPIT];
    __shared__ __nv_bfloat16 sBhi[128][SPIT];
    __shared__ __nv_bfloat16 sBlo[128][SPIT];

    int t = threadIdx.x;
    int lane = t & 31;
    int wid = t >> 5;
    int wm = wid & 3;
    int wn = wid >> 2;
    int node0 = blockIdx.x * 128;

    float acc[2][8][4];
#pragma unroll
    for (int i = 0; i < 2; i++)
#pragma unroll
        for (int j = 0; j < 8; j++)
#pragma unroll
            for (int q = 0; q < 4; q++) acc[i][j][q] = 0.0f;

    for (int k0 = 0; k0 < IN_F; k0 += 32) {
#pragma unroll
        for (int j = 0; j < 4; j++) {
            int id = t + j * 256;            // 0..1023
            int row = id >> 3;
            int c4 = (id & 7) * 4;
            int node = node0 + row;
            if (node >= NN) node = NN - 1;
            float4 v = *(const float4*)(feat + (long)node * IN_F + k0 + c4);
            bsplit(v.x, sAhi[row][c4 + 0], sAlo[row][c4 + 0]);
            bsplit(v.y, sAhi[row][c4 + 1], sAlo[row][c4 + 1]);
            bsplit(v.z, sAhi[row][c4 + 2], sAlo[row][c4 + 2]);
            bsplit(v.w, sAhi[row][c4 + 3], sAlo[row][c4 + 3]);
        }
#pragma unroll
        for (int j = 0; j < 4; j++) {
            int id = t + j * 256;
            int row = id >> 3;
            int c4 = (id & 7) * 4;
            float4 v = *(const float4*)(W + (long)row * IN_F + k0 + c4);
            bsplit(v.x, sBhi[row][c4 + 0], sBlo[row][c4 + 0]);
            bsplit(v.y, sBhi[row][c4 + 1], sBlo[row][c4 + 1]);
            bsplit(v.z, sBhi[row][c4 + 2], sBlo[row][c4 + 2]);
            bsplit(v.w, sBhi[row][c4 + 3], sBlo[row][c4 + 3]);
        }
        __syncthreads();

#pragma unroll
        for (int ks = 0; ks < 2; ks++) {
            int koff = ks * 16;
            unsigned ahi[2][4], alo[2][4];
#pragma unroll
            for (int mt = 0; mt < 2; mt++) {
                int row = wm * 32 + mt * 16 + (lane & 15);
                int col = koff + (lane >> 4) * 8;
                ldm_x4(ahi[mt], &sAhi[row][col]);
                ldm_x4(alo[mt], &sAlo[row][col]);
            }
            unsigned bhi[4][4], blo[4][4];
#pragma unroll
            for (int ng = 0; ng < 4; ng++) {
                int row = wn * 64 + ng * 16 + (lane & 7) + ((lane >> 4) << 3);
                int col = koff + ((lane >> 3) & 1) * 8;
                ldm_x4(bhi[ng], &sBhi[row][col]);
                ldm_x4(blo[ng], &sBlo[row][col]);
            }
#pragma unroll
            for (int mt = 0; mt < 2; mt++)
#pragma unroll
                for (int ng = 0; ng < 4; ng++)
#pragma unroll
                    for (int hf = 0; hf < 2; hf++) {
                        float* c = acc[mt][ng * 2 + hf];
                        mma16816(c, ahi[mt], bhi[ng][hf * 2], bhi[ng][hf * 2 + 1]);
                        mma16816(c, ahi[mt], blo[ng][hf * 2], blo[ng][hf * 2 + 1]);
                        mma16816(c, alo[mt], bhi[ng][hf * 2], bhi[ng][hf * 2 + 1]);
                    }
        }
        __syncthreads();
    }

    // epilogue: g_hh (fp16) stores + fused el/er
    int grp = lane >> 2;
    int tg = lane & 3;
    float pl[2][2][2];   // [mt][rowsel][head_in_warp]
    float pr[2][2][2];
#pragma unroll
    for (int a = 0; a < 2; a++)
#pragma unroll
        for (int b = 0; b < 2; b++)
#pragma unroll
            for (int c = 0; c < 2; c++) { pl[a][b][c] = 0.f; pr[a][b][c] = 0.f; }

#pragma unroll
    for (int mt = 0; mt < 2; mt++) {
        int row = node0 + wm * 32 + mt * 16 + grp;
#pragma unroll
        for (int nt = 0; nt < 8; nt++) {
            int col = wn * 64 + nt * 8 + tg * 2;
            int hi = nt >> 2;                 // head within this warp's pair
            float a0 = al[col], a1 = al[col + 1];
            float r0 = ar[col], r1 = ar[col + 1];
            float* c = acc[mt][nt];
            pl[mt][0][hi] += c[0] * a0 + c[1] * a1;
            pr[mt][0][hi] += c[0] * r0 + c[1] * r1;
            pl[mt][1][hi] += c[2] * a0 + c[3] * a1;
            pr[mt][1][hi] += c[2] * r0 + c[3] * r1;
            if (row < NN)
                *(__half2*)(g_hh + (long)row * OUT_C + col) = __floats2half2_rn(c[0], c[1]);
            if (row + 8 < NN)
                *(__half2*)(g_hh + (long)(row + 8) * OUT_C + col) = __floats2half2_rn(c[2], c[3]);
        }
    }

    // reduce over the 4-lane tg group (lanes grp*4 .. grp*4+3)
#pragma unroll
    for (int mt = 0; mt < 2; mt++)
#pragma unroll
        for (int rs = 0; rs < 2; rs++)
#pragma unroll
            for (int hi = 0; hi < 2; hi++) {
                float vl = pl[mt][rs][hi];
                float vr = pr[mt][rs][hi];
                vl += __shfl_xor_sync(0xffffffffu, vl, 1);
                vl += __shfl_xor_sync(0xffffffffu, vl, 2);
                vr += __shfl_xor_sync(0xffffffffu, vr, 1);
                vr += __shfl_xor_sync(0xffffffffu, vr, 2);
                if (tg == 0) {
                    int node = node0 + wm * 32 + mt * 16 + grp + rs * 8;
                    int head = wn * 2 + hi;
                    if (node < NN) {
                        g_el[node * NH + head] = vl;
                        g_er[node * NH + head] = vr;
                    }
                }
            }
}

// ---------------------------------------------------------------------------
// Fused softmax + aggregation: single-phase, half-warp per edge, FFMA2 accs.
// ---------------------------------------------------------------------------
__global__ __launch_bounds__(256) void agg_kernel(const float* __restrict__ bias,
                                                  float* __restrict__ out)
{
    int wib  = threadIdx.x >> 5;
    int lane = threadIdx.x & 31;
    int node = blockIdx.x * 8 + wib;
    if (node >= NN) return;

    int beg = g_off[node];
    int end = g_off[node + 1];

    int half = lane >> 4;      // which edge of the pair
    int hl   = lane & 15;      // lane within half-warp
    int hd2  = hl >> 2;        // head for my column range

    const float erv = g_er[node * NH + hd2];

    float dsum = 0.f;
    u64 acc2[4];
#pragma unroll
    for (int k = 0; k < 4; k++) acc2[k] = 0ull;   // packed (0.f, 0.f)

    const long colo = (long)hl * 8;   // fp16 column offset for this lane

    int e0 = beg;
    for (; e0 + 3 < end; e0 += 4) {
        int eA = e0 + half * 2;
        int sA = g_csr_src[eA];
        int sB = g_csr_src[eA + 1];
        float lA = g_el[sA * NH + hd2];
        float lB = g_el[sB * NH + hd2];
        uint4 hA = *(const uint4*)((const char*)g_hh + ((long)sA * OUT_C + colo) * 2);
        uint4 hB = *(const uint4*)((const char*)g_hh + ((long)sB * OUT_C + colo) * 2);

        float xA = lA + erv; xA = xA >= 0.f ? xA : NEG * xA;
        float xB = lB + erv; xB = xB >= 0.f ? xB : NEG * xB;
        float aA = __expf(xA);
        float aB = __expf(xB);
        dsum += aA + aB;

        u64 aA2, aB2;
        PACKF2(aA2, aA, aA);
        PACKF2(aB2, aB, aB);

        float2 f; u64 p;
        f = __half22float2(*(const __half2*)&hA.x); PACKF2(p, f.x, f.y); FMA2(acc2[0], p, aA2, acc2[0]);
        f = __half22float2(*(const __half2*)&hA.y); PACKF2(p, f.x, f.y); FMA2(acc2[1], p, aA2, acc2[1]);
        f = __half22float2(*(const __half2*)&hA.z); PACKF2(p, f.x, f.y); FMA2(acc2[2], p, aA2, acc2[2]);
        f = __half22float2(*(const __half2*)&hA.w); PACKF2(p, f.x, f.y); FMA2(acc2[3], p, aA2, acc2[3]);
        f = __half22float2(*(const __half2*)&hB.x); PACKF2(p, f.x, f.y); FMA2(acc2[0], p, aB2, acc2[0]);
        f = __half22float2(*(const __half2*)&hB.y); PACKF2(p, f.x, f.y); FMA2(acc2[1], p, aB2, acc2[1]);
        f = __half22float2(*(const __half2*)&hB.z); PACKF2(p, f.x, f.y); FMA2(acc2[2], p, aB2, acc2[2]);
        f = __half22float2(*(const __half2*)&hB.w); PACKF2(p, f.x, f.y); FMA2(acc2[3], p, aB2, acc2[3]);
    }
    for (; e0 < end; e0 += 2) {
        int e = e0 + half;
        if (e < end) {
            int s = g_csr_src[e];
            float l = g_el[s * NH + hd2];
            uint4 hv = *(const uint4*)((const char*)g_hh + ((long)s * OUT_C + colo) * 2);
            float x = l + erv; x = x >= 0.f ? x : NEG * x;
            float a = __expf(x);
            dsum += a;
            u64 a2;
            PACKF2(a2, a, a);
            float2 f; u64 p;
            f = __half22float2(*(const __half2*)&hv.x); PACKF2(p, f.x, f.y); FMA2(acc2[0], p, a2, acc2[0]);
            f = __half22float2(*(const __half2*)&hv.y); PACKF2(p, f.x, f.y); FMA2(acc2[1], p, a2, acc2[1]);
            f = __half22float2(*(const __half2*)&hv.z); PACKF2(p, f.x, f.y); FMA2(acc2[2], p, a2, acc2[2]);
            f = __half22float2(*(const __half2*)&hv.w); PACKF2(p, f.x, f.y); FMA2(acc2[3], p, a2, acc2[3]);
        }
    }

    float acc8[8];
#pragma unroll
    for (int k = 0; k < 4; k++) {
        UNPACKF2(acc8[k * 2], acc8[k * 2 + 1], acc2[k]);
    }

#pragma unroll
    for (int k = 0; k < 8; k++)
        acc8[k] += __shfl_xor_sync(0xffffffffu, acc8[k], 16);

    dsum += __shfl_xor_sync(0xffffffffu, dsum, 16);
    dsum += __shfl_xor_sync(0xffffffffu, dsum, 1);
    dsum += __shfl_xor_sync(0xffffffffu, dsum, 2);
    float dn = dsum * 0.25f;
    float rdn = (dn > 0.f) ? (1.0f / dn) : 1.0f;

    if (half == 0) {
        float4 b0 = *(const float4*)(bias + hl * 8);
        float4 b1 = *(const float4*)(bias + hl * 8 + 4);
        float4 o0, o1;
        o0.x = acc8[0] * rdn + b0.x; o0.y = acc8[1] * rdn + b0.y;
        o0.z = acc8[2] * rdn + b0.z; o0.w = acc8[3] * rdn + b0.w;
        o1.x = acc8[4] * rdn + b1.x; o1.y = acc8[5] * rdn + b1.y;
        o1.z = acc8[6] * rdn + b1.z; o1.w = acc8[7] * rdn + b1.w;
        *(float4*)(out + (long)node * OUT_C + hl * 8)     = o0;
        *(float4*)(out + (long)node * OUT_C + hl * 8 + 4) = o1;
    }
}

// ---------------------------------------------------------------------------
// Launch: fork-join; CSR build (s2) overlaps projection (main). 5 kernels
// before agg -> agg is the 6th execution and gets the ncu capture slot.
// ---------------------------------------------------------------------------
extern "C" void kernel_launch(void* const* d_in, const int* in_sizes, int n_in,
                              void* d_out, int out_size) {
    const float* feat = (const float*)d_in[0];
    const float* W    = (const float*)d_in[1];
    const float* al   = (const float*)d_in[2];
    const float* ar   = (const float*)d_in[3];
    const float* bias = (const float*)d_in[4];
    const int*   src  = (const int*)d_in[5];
    const int*   dst  = (const int*)d_in[6];
    float* out = (float*)d_out;

    static cudaStream_t s2 = nullptr;
    static cudaEvent_t ev_fork = nullptr, ev_join = nullptr;
    if (s2 == nullptr) {
        cudaStreamCreateWithFlags(&s2, cudaStreamNonBlocking);
        cudaEventCreateWithFlags(&ev_fork, cudaEventDisableTiming);
        cudaEventCreateWithFlags(&ev_join, cudaEventDisableTiming);
    }

    cudaEventRecord(ev_fork, 0);
    cudaStreamWaitEvent(s2, ev_fork, 0);

    // branch A (s2): CSR build (g_cnt arrives zeroed; scan1 re-zeroes it)
    hist_kernel<<<(NE / 8 + 255) / 256, 256, 0, s2>>>(dst);
    scan1_kernel<<<49, 1024, 0, s2>>>();
    scan3_kernel<<<49, 1024, 0, s2>>>();
    scatter_kernel<<<(NE / 8 + 255) / 256, 256, 0, s2>>>(src, dst);

    // branch B (main stream): projection + fused logits
    proj_mma_kernel<<<(NN + 127) / 128, 256>>>(feat, W, al, ar);

    cudaEventRecord(ev_join, s2);
    cudaStreamWaitEvent(0, ev_join, 0);

    agg_kernel<<<(NN + 7) / 8, 256>>>(bias, out);
}

// round 17
// speedup vs baseline: 1.1433x; 1.0146x over previous
#include <cuda_runtime.h>
#include <cuda_bf16.h>
#include <cuda_fp16.h>
#include <cstdint>

#define NN 50000
#define NE 1600000
#define IN_F 256
#define OUT_C 128   // H*F
#define NH 4
#define NEG 0.2f

typedef unsigned long long u64;

// scratch (allocation-free rule: __device__ globals)
__device__ __align__(16) __half g_hh[NN * OUT_C];    // projected features fp16 [N,128]
__device__ __align__(16) float  g_el[NN * NH];       // left logits  [N,4]
__device__ __align__(16) float  g_er[NN * NH];       // right logits [N,4]
__device__ int g_cnt[NN];                            // in-degree histogram (zero-init; re-zeroed by scan)
__device__ int g_off[NN + 1];                        // CSR offsets (by dst)
__device__ int g_cur[NN];                            // scatter cursors (= g_off at scan end)
__device__ int g_bsum[64];                           // per-block scan totals
__device__ int g_flag[64];                           // lookback flags (reset by scatter)
__device__ int g_csr_src[NE];                        // src node per CSR slot

// packed fp32x2 FMA (sm_103a FFMA2; only reachable via PTX)
#define FMA2(d, a, b, c) \
    asm("fma.rn.f32x2 %0, %1, %2, %3;" : "=l"(d) : "l"(a), "l"(b), "l"(c))
#define PACKF2(d, lo, hi) \
    asm("mov.b64 %0, {%1, %2};" : "=l"(d) : "f"(lo), "f"(hi))
#define UNPACKF2(lo, hi, s) \
    asm("mov.b64 {%0, %1}, %2;" : "=f"(lo), "=f"(hi) : "l"(s))

// ---------------------------------------------------------------------------
// CSR build: hist (pure RED) -> lookback scan (off+cur, re-zeroes cnt)
//            -> scatter (atomic slot claim, resets flags)
// ---------------------------------------------------------------------------
__global__ void hist_kernel(const int* __restrict__ dst) {
    int base = (blockIdx.x * blockDim.x + threadIdx.x) * 8;
    if (base >= NE) return;
    int4 d0 = *(const int4*)(dst + base);
    int4 d1 = *(const int4*)(dst + base + 4);
    int d[8] = {d0.x, d0.y, d0.z, d0.w, d1.x, d1.y, d1.z, d1.w};
#pragma unroll
    for (int j = 0; j < 8; j++) atomicAdd(&g_cnt[d[j]], 1);   // return unused -> RED
}

// Single-pass scan with decoupled lookback (49 blocks, all lower-bid blocks
// dispatch first -> forward progress). Publishes per-block totals; block b's
// threads t<b poll predecessors in parallel, tree-reduce the prefix.
__global__ __launch_bounds__(1024) void scan_kernel() {
    __shared__ int ssum[1024];
    __shared__ int sadd[64];
    int b = blockIdx.x, t = threadIdx.x;
    int i = b * 1024 + t;
    int c = 0;
    if (i < NN) {
        c = g_cnt[i];
        g_cnt[i] = 0;          // self-restore for next replay
    }
    ssum[t] = c;
    __syncthreads();
    for (int off = 1; off < 1024; off <<= 1) {
        int v = (t >= off) ? ssum[t - off] : 0;
        __syncthreads();
        ssum[t] += v;
        __syncthreads();
    }
    // publish this block's total
    if (t == 1023) {
        g_bsum[b] = ssum[1023];
        __threadfence();
        *((volatile int*)&g_flag[b]) = 1;
    }
    // parallel lookback: thread t (< b) waits for block t's total
    int v = 0;
    if (t < b) {
        while (*((volatile int*)&g_flag[t]) == 0) { }
        v = *((volatile int*)&g_bsum[t]);
    }
    if (t < 64) sadd[t] = (t < b) ? v : 0;
    __syncthreads();
#pragma unroll
    for (int off = 32; off >= 1; off >>= 1) {
        if (t < off) sadd[t] += sadd[t + off];
        __syncthreads();
    }
    int add = sadd[0];
    if (i <= NN) {
        int o = ssum[t] - c + add;   // global exclusive prefix (i==NN -> NE)
        g_off[i] = o;
        if (i < NN) g_cur[i] = o;
    }
}

__global__ void scatter_kernel(const int* __restrict__ src, const int* __restrict__ dst) {
    // reset lookback flags for the next replay (scan is stream-ordered before us)
    if (blockIdx.x == 0 && threadIdx.x < 64) g_flag[threadIdx.x] = 0;
    int base = (blockIdx.x * blockDim.x + threadIdx.x) * 8;
    if (base >= NE) return;
    int4 d0 = *(const int4*)(dst + base);
    int4 d1 = *(const int4*)(dst + base + 4);
    int4 s0 = *(const int4*)(src + base);
    int4 s1 = *(const int4*)(src + base + 4);
    int d[8] = {d0.x, d0.y, d0.z, d0.w, d1.x, d1.y, d1.z, d1.w};
    int s[8] = {s0.x, s0.y, s0.z, s0.w, s1.x, s1.y, s1.z, s1.w};
    int p[8];
#pragma unroll
    for (int j = 0; j < 8; j++) p[j] = atomicAdd(&g_cur[d[j]], 1);
#pragma unroll
    for (int j = 0; j < 8; j++) g_csr_src[p[j]] = s[j];
}

// ---------------------------------------------------------------------------
// Projection: h = feat @ W^T via bf16-split tensor-core GEMM.
// Epilogue fuses el/er (4-lane shfl reduce); fp32 h never materialized.
// ---------------------------------------------------------------------------
#define SPIT 40

__device__ __forceinline__ void bsplit(float x, __nv_bfloat16& hi, __nv_bfloat16& lo) {
    hi = __float2bfloat16_rn(x);
    lo = __float2bfloat16_rn(x - __bfloat162float(hi));
}

__device__ __forceinline__ void ldm_x4(unsigned* r, const __nv_bfloat16* p) {
    unsigned a = (unsigned)__cvta_generic_to_shared(p);
    asm volatile("ldmatrix.sync.aligned.m8n8.x4.shared.b16 {%0,%1,%2,%3}, [%4];"
                 : "=r"(r[0]), "=r"(r[1]), "=r"(r[2]), "=r"(r[3]) : "r"(a));
}

__device__ __forceinline__ void mma16816(float* c, const unsigned* a,
                                         unsigned b0, unsigned b1) {
    asm volatile("mma.sync.aligned.m16n8k16.row.col.f32.bf16.bf16.f32 "
                 "{%0,%1,%2,%3},{%4,%5,%6,%7},{%8,%9},{%0,%1,%2,%3};"
                 : "+f"(c[0]), "+f"(c[1]), "+f"(c[2]), "+f"(c[3])
                 : "r"(a[0]), "r"(a[1]), "r"(a[2]), "r"(a[3]), "r"(b0), "r"(b1));
}

__global__ __launch_bounds__(256) void proj_mma_kernel(
    const float* __restrict__ feat, const float* __restrict__ W,
    const float* __restrict__ al, const float* __restrict__ ar)
{
    __shared__ __nv_bfloat16 sAhi[128][SPIT];
    __shared__ __nv_bfloat16 sAlo[128][SPIT];
    __shared__ __nv_bfloat16 sBhi[128][SPIT];
    __shared__ __nv_bfloat16 sBlo[128][SPIT];

    int t = threadIdx.x;
    int lane = t & 31;
    int wid = t >> 5;
    int wm = wid & 3;
    int wn = wid >> 2;
    int node0 = blockIdx.x * 128;

    float acc[2][8][4];
#pragma unroll
    for (int i = 0; i < 2; i++)
#pragma unroll
        for (int j = 0; j < 8; j++)
#pragma unroll
            for (int q = 0; q < 4; q++) acc[i][j][q] = 0.0f;

    for (int k0 = 0; k0 < IN_F; k0 += 32) {
#pragma unroll
        for (int j = 0; j < 4; j++) {
            int id = t + j * 256;            // 0..1023
            int row = id >> 3;
            int c4 = (id & 7) * 4;
            int node = node0 + row;
            if (node >= NN) node = NN - 1;
            float4 v = *(const float4*)(feat + (long)node * IN_F + k0 + c4);
            bsplit(v.x, sAhi[row][c4 + 0], sAlo[row][c4 + 0]);
            bsplit(v.y, sAhi[row][c4 + 1], sAlo[row][c4 + 1]);
            bsplit(v.z, sAhi[row][c4 + 2], sAlo[row][c4 + 2]);
            bsplit(v.w, sAhi[row][c4 + 3], sAlo[row][c4 + 3]);
        }
#pragma unroll
        for (int j = 0; j < 4; j++) {
            int id = t + j * 256;
            int row = id >> 3;
            int c4 = (id & 7) * 4;
            float4 v = *(const float4*)(W + (long)row * IN_F + k0 + c4);
            bsplit(v.x, sBhi[row][c4 + 0], sBlo[row][c4 + 0]);
            bsplit(v.y, sBhi[row][c4 + 1], sBlo[row][c4 + 1]);
            bsplit(v.z, sBhi[row][c4 + 2], sBlo[row][c4 + 2]);
            bsplit(v.w, sBhi[row][c4 + 3], sBlo[row][c4 + 3]);
        }
        __syncthreads();

#pragma unroll
        for (int ks = 0; ks < 2; ks++) {
            int koff = ks * 16;
            unsigned ahi[2][4], alo[2][4];
#pragma unroll
            for (int mt = 0; mt < 2; mt++) {
                int row = wm * 32 + mt * 16 + (lane & 15);
                int col = koff + (lane >> 4) * 8;
                ldm_x4(ahi[mt], &sAhi[row][col]);
                ldm_x4(alo[mt], &sAlo[row][col]);
            }
            unsigned bhi[4][4], blo[4][4];
#pragma unroll
            for (int ng = 0; ng < 4; ng++) {
                int row = wn * 64 + ng * 16 + (lane & 7) + ((lane >> 4) << 3);
                int col = koff + ((lane >> 3) & 1) * 8;
                ldm_x4(bhi[ng], &sBhi[row][col]);
                ldm_x4(blo[ng], &sBlo[row][col]);
            }
#pragma unroll
            for (int mt = 0; mt < 2; mt++)
#pragma unroll
                for (int ng = 0; ng < 4; ng++)
#pragma unroll
                    for (int hf = 0; hf < 2; hf++) {
                        float* c = acc[mt][ng * 2 + hf];
                        mma16816(c, ahi[mt], bhi[ng][hf * 2], bhi[ng][hf * 2 + 1]);
                        mma16816(c, ahi[mt], blo[ng][hf * 2], blo[ng][hf * 2 + 1]);
                        mma16816(c, alo[mt], bhi[ng][hf * 2], bhi[ng][hf * 2 + 1]);
                    }
        }
        __syncthreads();
    }

    // epilogue: g_hh (fp16) stores + fused el/er
    int grp = lane >> 2;
    int tg = lane & 3;
    float pl[2][2][2];   // [mt][rowsel][head_in_warp]
    float pr[2][2][2];
#pragma unroll
    for (int a = 0; a < 2; a++)
#pragma unroll
        for (int b = 0; b < 2; b++)
#pragma unroll
            for (int c = 0; c < 2; c++) { pl[a][b][c] = 0.f; pr[a][b][c] = 0.f; }

#pragma unroll
    for (int mt = 0; mt < 2; mt++) {
        int row = node0 + wm * 32 + mt * 16 + grp;
#pragma unroll
        for (int nt = 0; nt < 8; nt++) {
            int col = wn * 64 + nt * 8 + tg * 2;
            int hi = nt >> 2;                 // head within this warp's pair
            float a0 = al[col], a1 = al[col + 1];
            float r0 = ar[col], r1 = ar[col + 1];
            float* c = acc[mt][nt];
            pl[mt][0][hi] += c[0] * a0 + c[1] * a1;
            pr[mt][0][hi] += c[0] * r0 + c[1] * r1;
            pl[mt][1][hi] += c[2] * a0 + c[3] * a1;
            pr[mt][1][hi] += c[2] * r0 + c[3] * r1;
            if (row < NN)
                *(__half2*)(g_hh + (long)row * OUT_C + col) = __floats2half2_rn(c[0], c[1]);
            if (row + 8 < NN)
                *(__half2*)(g_hh + (long)(row + 8) * OUT_C + col) = __floats2half2_rn(c[2], c[3]);
        }
    }

    // reduce over the 4-lane tg group (lanes grp*4 .. grp*4+3)
#pragma unroll
    for (int mt = 0; mt < 2; mt++)
#pragma unroll
        for (int rs = 0; rs < 2; rs++)
#pragma unroll
            for (int hi = 0; hi < 2; hi++) {
                float vl = pl[mt][rs][hi];
                float vr = pr[mt][rs][hi];
                vl += __shfl_xor_sync(0xffffffffu, vl, 1);
                vl += __shfl_xor_sync(0xffffffffu, vl, 2);
                vr += __shfl_xor_sync(0xffffffffu, vr, 1);
                vr += __shfl_xor_sync(0xffffffffu, vr, 2);
                if (tg == 0) {
                    int node = node0 + wm * 32 + mt * 16 + grp + rs * 8;
                    int head = wn * 2 + hi;
                    if (node < NN) {
                        g_el[node * NH + head] = vl;
                        g_er[node * NH + head] = vr;
                    }
                }
            }
}

// ---------------------------------------------------------------------------
// Fused softmax + aggregation: single-phase, half-warp per edge, FFMA2 accs.
// ---------------------------------------------------------------------------
__global__ __launch_bounds__(256) void agg_kernel(const float* __restrict__ bias,
                                                  float* __restrict__ out)
{
    int wib  = threadIdx.x >> 5;
    int lane = threadIdx.x & 31;
    int node = blockIdx.x * 8 + wib;
    if (node >= NN) return;

    int beg = g_off[node];
    int end = g_off[node + 1];

    int half = lane >> 4;      // which edge of the pair
    int hl   = lane & 15;      // lane within half-warp
    int hd2  = hl >> 2;        // head for my column range

    const float erv = g_er[node * NH + hd2];

    float dsum = 0.f;
    u64 acc2[4];
#pragma unroll
    for (int k = 0; k < 4; k++) acc2[k] = 0ull;   // packed (0.f, 0.f)

    const long colo = (long)hl * 8;   // fp16 column offset for this lane

    int e0 = beg;
    for (; e0 + 3 < end; e0 += 4) {
        int eA = e0 + half * 2;
        int sA = g_csr_src[eA];
        int sB = g_csr_src[eA + 1];
        float lA = g_el[sA * NH + hd2];
        float lB = g_el[sB * NH + hd2];
        uint4 hA = *(const uint4*)((const char*)g_hh + ((long)sA * OUT_C + colo) * 2);
        uint4 hB = *(const uint4*)((const char*)g_hh + ((long)sB * OUT_C + colo) * 2);

        float xA = lA + erv; xA = xA >= 0.f ? xA : NEG * xA;
        float xB = lB + erv; xB = xB >= 0.f ? xB : NEG * xB;
        float aA = __expf(xA);
        float aB = __expf(xB);
        dsum += aA + aB;

        u64 aA2, aB2;
        PACKF2(aA2, aA, aA);
        PACKF2(aB2, aB, aB);

        float2 f; u64 p;
        f = __half22float2(*(const __half2*)&hA.x); PACKF2(p, f.x, f.y); FMA2(acc2[0], p, aA2, acc2[0]);
        f = __half22float2(*(const __half2*)&hA.y); PACKF2(p, f.x, f.y); FMA2(acc2[1], p, aA2, acc2[1]);
        f = __half22float2(*(const __half2*)&hA.z); PACKF2(p, f.x, f.y); FMA2(acc2[2], p, aA2, acc2[2]);
        f = __half22float2(*(const __half2*)&hA.w); PACKF2(p, f.x, f.y); FMA2(acc2[3], p, aA2, acc2[3]);
        f = __half22float2(*(const __half2*)&hB.x); PACKF2(p, f.x, f.y); FMA2(acc2[0], p, aB2, acc2[0]);
        f = __half22float2(*(const __half2*)&hB.y); PACKF2(p, f.x, f.y); FMA2(acc2[1], p, aB2, acc2[1]);
        f = __half22float2(*(const __half2*)&hB.z); PACKF2(p, f.x, f.y); FMA2(acc2[2], p, aB2, acc2[2]);
        f = __half22float2(*(const __half2*)&hB.w); PACKF2(p, f.x, f.y); FMA2(acc2[3], p, aB2, acc2[3]);
    }
    for (; e0 < end; e0 += 2) {
        int e = e0 + half;
        if (e < end) {
            int s = g_csr_src[e];
            float l = g_el[s * NH + hd2];
            uint4 hv = *(const uint4*)((const char*)g_hh + ((long)s * OUT_C + colo) * 2);
            float x = l + erv; x = x >= 0.f ? x : NEG * x;
            float a = __expf(x);
            dsum += a;
            u64 a2;
            PACKF2(a2, a, a);
            float2 f; u64 p;
            f = __half22float2(*(const __half2*)&hv.x); PACKF2(p, f.x, f.y); FMA2(acc2[0], p, a2, acc2[0]);
            f = __half22float2(*(const __half2*)&hv.y); PACKF2(p, f.x, f.y); FMA2(acc2[1], p, a2, acc2[1]);
            f = __half22float2(*(const __half2*)&hv.z); PACKF2(p, f.x, f.y); FMA2(acc2[2], p, a2, acc2[2]);
            f = __half22float2(*(const __half2*)&hv.w); PACKF2(p, f.x, f.y); FMA2(acc2[3], p, a2, acc2[3]);
        }
    }

    float acc8[8];
#pragma unroll
    for (int k = 0; k < 4; k++) {
        UNPACKF2(acc8[k * 2], acc8[k * 2 + 1], acc2[k]);
    }

#pragma unroll
    for (int k = 0; k < 8; k++)
        acc8[k] += __shfl_xor_sync(0xffffffffu, acc8[k], 16);

    dsum += __shfl_xor_sync(0xffffffffu, dsum, 16);
    dsum += __shfl_xor_sync(0xffffffffu, dsum, 1);
    dsum += __shfl_xor_sync(0xffffffffu, dsum, 2);
    float dn = dsum * 0.25f;
    float rdn = (dn > 0.f) ? (1.0f / dn) : 1.0f;

    if (half == 0) {
        float4 b0 = *(const float4*)(bias + hl * 8);
        float4 b1 = *(const float4*)(bias + hl * 8 + 4);
        float4 o0, o1;
        o0.x = acc8[0] * rdn + b0.x; o0.y = acc8[1] * rdn + b0.y;
        o0.z = acc8[2] * rdn + b0.z; o0.w = acc8[3] * rdn + b0.w;
        o1.x = acc8[4] * rdn + b1.x; o1.y = acc8[5] * rdn + b1.y;
        o1.z = acc8[6] * rdn + b1.z; o1.w = acc8[7] * rdn + b1.w;
        *(float4*)(out + (long)node * OUT_C + hl * 8)     = o0;
        *(float4*)(out + (long)node * OUT_C + hl * 8 + 4) = o1;
    }
}

// ---------------------------------------------------------------------------
// Launch: fork-join; CSR build (s2, 3 kernels) overlaps projection (main).
// ---------------------------------------------------------------------------
extern "C" void kernel_launch(void* const* d_in, const int* in_sizes, int n_in,
                              void* d_out, int out_size) {
    const float* feat = (const float*)d_in[0];
    const float* W    = (const float*)d_in[1];
    const float* al   = (const float*)d_in[2];
    const float* ar   = (const float*)d_in[3];
    const float* bias = (const float*)d_in[4];
    const int*   src  = (const int*)d_in[5];
    const int*   dst  = (const int*)d_in[6];
    float* out = (float*)d_out;

    static cudaStream_t s2 = nullptr;
    static cudaEvent_t ev_fork = nullptr, ev_join = nullptr;
    if (s2 == nullptr) {
        cudaStreamCreateWithFlags(&s2, cudaStreamNonBlocking);
        cudaEventCreateWithFlags(&ev_fork, cudaEventDisableTiming);
        cudaEventCreateWithFlags(&ev_join, cudaEventDisableTiming);
    }

    cudaEventRecord(ev_fork, 0);
    cudaStreamWaitEvent(s2, ev_fork, 0);

    // branch A (s2): CSR build
    hist_kernel<<<(NE / 8 + 255) / 256, 256, 0, s2>>>(dst);
    scan_kernel<<<49, 1024, 0, s2>>>();
    scatter_kernel<<<(NE / 8 + 255) / 256, 256, 0, s2>>>(src, dst);

    // branch B (main stream): projection + fused logits
    proj_mma_kernel<<<(NN + 127) / 128, 256>>>(feat, W, al, ar);

    cudaEventRecord(ev_join, s2);
    cudaStreamWaitEvent(0, ev_join, 0);

    agg_kernel<<<(NN + 7) / 8, 256>>>(bias, out);
}